// round 4
// baseline (speedup 1.0000x reference)
#include <cuda_runtime.h>

#define NN 512
#define CC 64
#define HH 256
#define EPSF 1e-5f

typedef unsigned long long u64;

// ---------------- packed f32x2 helpers (sm_100+) ----------------
__device__ __forceinline__ u64 pk(float lo, float hi) {
    u64 r; asm("mov.b64 %0,{%1,%2};" : "=l"(r) : "f"(lo), "f"(hi)); return r;
}
__device__ __forceinline__ void unpk(u64 v, float& lo, float& hi) {
    asm("mov.b64 {%0,%1},%2;" : "=f"(lo), "=f"(hi) : "l"(v));
}
__device__ __forceinline__ u64 add2(u64 a, u64 b) {
    u64 r; asm("add.rn.f32x2 %0,%1,%2;" : "=l"(r) : "l"(a), "l"(b)); return r;
}
__device__ __forceinline__ u64 mul2(u64 a, u64 b) {
    u64 r; asm("mul.rn.f32x2 %0,%1,%2;" : "=l"(r) : "l"(a), "l"(b)); return r;
}
__device__ __forceinline__ u64 fma2(u64 a, u64 b, u64 c) {
    u64 r; asm("fma.rn.f32x2 %0,%1,%2,%3;" : "=l"(r) : "l"(a), "l"(b), "l"(c)); return r;
}
__device__ __forceinline__ float ex2f(float x) {
    float r; asm("ex2.approx.f32 %0,%1;" : "=f"(r) : "f"(x)); return r;
}
__device__ __forceinline__ float warp_sum(float x) {
#pragma unroll
    for (int off = 16; off > 0; off >>= 1)
        x += __shfl_xor_sync(0xffffffffu, x, off);
    return x;
}

// ---------------- scratch (device globals; no allocs allowed) ----------------
__device__ float g_T[2][NN][768];   // T_A = xl@[W0|W2|W4], T_B = xr@[W1|W3|W5]
__device__ float g_RA [NN*HH];
__device__ float g_RB [NN*HH];
__device__ float g_A1M[NN*HH];
__device__ float g_A2P[NN*HH];
__device__ float g_B1P[NN*HH];
__device__ float g_B2M[NN*HH];
__device__ float g_SA[NN];
__device__ float g_SB[NN];

// ---------------------------------------------------------------------------
// Stage 1: tiled GEMM. M=512, N=768, K=64, two batches (xl / xr).
// ---------------------------------------------------------------------------
__global__ __launch_bounds__(256) void gemm_pre_kernel(
    const float* __restrict__ xl, const float* __restrict__ xr,
    const float* __restrict__ W1)
{
    __shared__ float Xs[64][68];
    __shared__ float Ws[64][68];

    const int z  = blockIdx.z;
    const float* X = z ? xr : xl;
    const int m0 = blockIdx.x * 64;
    const int n0 = blockIdx.y * 64;
    const int sel = n0 >> 8;
    const int h0  = n0 & 255;
    const float* Wbase = W1 + ((2 * sel + z) * 64) * HH + h0;

    const int t = threadIdx.x;
    {
        int f = t & 63, i0 = t >> 6;
#pragma unroll
        for (int ii = 0; ii < 64; ii += 4)
            Xs[f][i0 + ii] = X[(m0 + i0 + ii) * CC + f];
    }
    {
        int n = t & 63, f0 = t >> 6;
#pragma unroll
        for (int ff = 0; ff < 64; ff += 4)
            Ws[f0 + ff][n] = Wbase[(f0 + ff) * HH + n];
    }
    __syncthreads();

    const int tx = t & 15, ty = t >> 4;
    float acc[4][4] = {};
#pragma unroll 16
    for (int k = 0; k < 64; k++) {
        float4 xa = *reinterpret_cast<const float4*>(&Xs[k][4 * ty]);
        float4 wb = *reinterpret_cast<const float4*>(&Ws[k][4 * tx]);
        float xr4[4] = {xa.x, xa.y, xa.z, xa.w};
        float wr4[4] = {wb.x, wb.y, wb.z, wb.w};
#pragma unroll
        for (int r = 0; r < 4; r++)
#pragma unroll
            for (int c = 0; c < 4; c++)
                acc[r][c] = fmaf(xr4[r], wr4[c], acc[r][c]);
    }
#pragma unroll
    for (int r = 0; r < 4; r++) {
        float4 v = make_float4(acc[r][0], acc[r][1], acc[r][2], acc[r][3]);
        *reinterpret_cast<float4*>(&g_T[z][m0 + 4 * ty + r][n0 + 4 * tx]) = v;
    }
}

// ---------------------------------------------------------------------------
// Stage 2: combine shifts + b1 into RA/RB (+masked parts) and row sums SA/SB.
// ---------------------------------------------------------------------------
__global__ __launch_bounds__(256) void combine_kernel(const float* __restrict__ b1)
{
    __shared__ float smA[8], smB[8];
    const int i = blockIdx.x, h = threadIdx.x;
    const int lane = h & 31, w = h >> 5;

    float a0  = g_T[0][i][h];
    float a1m = (i > 0)      ? g_T[0][i - 1][256 + h] : 0.f;
    float a2p = (i < NN - 1) ? g_T[0][i + 1][512 + h] : 0.f;
    float ra  = a0 + b1[h] + a1m + a2p;
    g_A1M[i * HH + h] = a1m;
    g_A2P[i * HH + h] = a2p;
    g_RA [i * HH + h] = ra;

    float b0  = g_T[1][i][h];
    float b1p = (i < NN - 1) ? g_T[1][i + 1][256 + h] : 0.f;
    float b2m = (i > 0)      ? g_T[1][i - 1][512 + h] : 0.f;
    float rb  = b0 + b1p + b2m;
    g_B1P[i * HH + h] = b1p;
    g_B2M[i * HH + h] = b2m;
    g_RB [i * HH + h] = rb;

    float sa = warp_sum(ra);
    float sb = warp_sum(rb);
    if (lane == 0) { smA[w] = sa; smB[w] = sb; }
    __syncthreads();
    if (h == 0) {
        float ta = 0.f, tb = 0.f;
#pragma unroll
        for (int k = 0; k < 8; k++) { ta += smA[k]; tb += smB[k]; }
        g_SA[i] = ta; g_SB[i] = tb;
    }
}

// ---------------------------------------------------------------------------
// Stage 3: main pairwise kernel (borders handled inline, warp-uniform branch).
// Interior: s = RA[i]+RB[j].  Border cells (i in {0,511} or j in {0,511}):
//   s -= cu*(A1M[i]+B1P[j]) + cd*(A2P[i]+B2M[j]).
// Epilogue: LN + CELU (log2e domain) + dot(W2), all f32x2-packed.
// ---------------------------------------------------------------------------
__global__ __launch_bounds__(256) void pair_main_kernel(
    const float* __restrict__ gamma, const float* __restrict__ beta,
    const float* __restrict__ W2, const float* __restrict__ b2,
    float* __restrict__ out)
{
    __shared__ float4 sA[16 * 64];
    __shared__ float4 sB[16 * 64];
    __shared__ float  sSA[16], sSB[16], sOut[256];

    const int t  = threadIdx.x;
    const int i0 = blockIdx.y * 16, j0 = blockIdx.x * 16;
    const bool blkBorder = (i0 == 0) | (i0 == NN - 16) | (j0 == 0) | (j0 == NN - 16);

    const float4* gA = reinterpret_cast<const float4*>(g_RA) + i0 * 64;
    const float4* gB = reinterpret_cast<const float4*>(g_RB) + j0 * 64;
#pragma unroll
    for (int k = 0; k < 4; k++) {
        sA[t + 256 * k] = gA[t + 256 * k];
        sB[t + 256 * k] = gB[t + 256 * k];
    }
    if (t < 16)      sSA[t]      = g_SA[i0 + t];
    else if (t < 32) sSB[t - 16] = g_SB[j0 + t - 16];

    const int lane = t & 31, w = t >> 5;
    const int c0 = 4 * lane, c1 = 128 + 4 * lane;
    const float L2E  = 1.4426950408889634f;
    const float IL2E = 0.6931471805599453f;

    u64 g2[4], be2[4], wm2[4], we2[4];
    float w2loc;
    {
        float4 gv0 = *reinterpret_cast<const float4*>(gamma + c0);
        float4 gv1 = *reinterpret_cast<const float4*>(gamma + c1);
        float4 bv0 = *reinterpret_cast<const float4*>(beta  + c0);
        float4 bv1 = *reinterpret_cast<const float4*>(beta  + c1);
        float4 wv0 = *reinterpret_cast<const float4*>(W2    + c0);
        float4 wv1 = *reinterpret_cast<const float4*>(W2    + c1);
        g2 [0] = pk(gv0.x * L2E, gv0.y * L2E);  g2 [1] = pk(gv0.z * L2E, gv0.w * L2E);
        g2 [2] = pk(gv1.x * L2E, gv1.y * L2E);  g2 [3] = pk(gv1.z * L2E, gv1.w * L2E);
        be2[0] = pk(bv0.x * L2E, bv0.y * L2E);  be2[1] = pk(bv0.z * L2E, bv0.w * L2E);
        be2[2] = pk(bv1.x * L2E, bv1.y * L2E);  be2[3] = pk(bv1.z * L2E, bv1.w * L2E);
        wm2[0] = pk(wv0.x * IL2E, wv0.y * IL2E); wm2[1] = pk(wv0.z * IL2E, wv0.w * IL2E);
        wm2[2] = pk(wv1.x * IL2E, wv1.y * IL2E); wm2[3] = pk(wv1.z * IL2E, wv1.w * IL2E);
        we2[0] = pk(wv0.x, wv0.y);  we2[1] = pk(wv0.z, wv0.w);
        we2[2] = pk(wv1.x, wv1.y);  we2[3] = pk(wv1.z, wv1.w);
        w2loc = ((wv0.x + wv0.y) + (wv0.z + wv0.w)) + ((wv1.x + wv1.y) + (wv1.z + wv1.w));
    }
    const float CADD = b2[0] - warp_sum(w2loc);
    __syncthreads();

    const ulonglong2* uA = reinterpret_cast<const ulonglong2*>(sA);
    const ulonglong2* uB = reinterpret_cast<const ulonglong2*>(sB);

#pragma unroll 2
    for (int k = 0; k < 32; k++) {
        int cidx = k * 8 + w;
        int li = cidx >> 4, lj = cidx & 15;
        ulonglong2 au0 = uA[li * 64 + lane];
        ulonglong2 au1 = uA[li * 64 + 32 + lane];
        ulonglong2 bu0 = uB[lj * 64 + lane];
        ulonglong2 bu1 = uB[lj * 64 + 32 + lane];
        u64 s2[4];
        s2[0] = add2(au0.x, bu0.x);
        s2[1] = add2(au0.y, bu0.y);
        s2[2] = add2(au1.x, bu1.x);
        s2[3] = add2(au1.y, bu1.y);

        float sum = sSA[li] + sSB[lj];

        if (blkBorder) {                       // warp-uniform (warp == cell)
            int gi = i0 + li, gj = j0 + lj;
            bool cu = (gi == 0) | (gj == NN - 1);
            bool cd = (gi == NN - 1) | (gj == 0);
            if (cu | cd) {
                const float4* A1 = reinterpret_cast<const float4*>(g_A1M + gi * HH);
                const float4* A2 = reinterpret_cast<const float4*>(g_A2P + gi * HH);
                const float4* B1 = reinterpret_cast<const float4*>(g_B1P + gj * HH);
                const float4* B2 = reinterpret_cast<const float4*>(g_B2M + gj * HH);
                float4 x0, x1, y0, y1;
                u64 mcu = pk(cu ? -1.f : 0.f, cu ? -1.f : 0.f);
                u64 mcd = pk(cd ? -1.f : 0.f, cd ? -1.f : 0.f);
                x0 = A1[lane]; x1 = A1[32 + lane];
                y0 = B1[lane]; y1 = B1[32 + lane];
                u64 u_[4] = { add2(pk(x0.x, x0.y), pk(y0.x, y0.y)),
                              add2(pk(x0.z, x0.w), pk(y0.z, y0.w)),
                              add2(pk(x1.x, x1.y), pk(y1.x, y1.y)),
                              add2(pk(x1.z, x1.w), pk(y1.z, y1.w)) };
#pragma unroll
                for (int p = 0; p < 4; p++) s2[p] = fma2(u_[p], mcu, s2[p]);
                x0 = A2[lane]; x1 = A2[32 + lane];
                y0 = B2[lane]; y1 = B2[32 + lane];
                u64 v_[4] = { add2(pk(x0.x, x0.y), pk(y0.x, y0.y)),
                              add2(pk(x0.z, x0.w), pk(y0.z, y0.w)),
                              add2(pk(x1.x, x1.y), pk(y1.x, y1.y)),
                              add2(pk(x1.z, x1.w), pk(y1.z, y1.w)) };
#pragma unroll
                for (int p = 0; p < 4; p++) s2[p] = fma2(v_[p], mcd, s2[p]);
                u64 ss = add2(add2(s2[0], s2[1]), add2(s2[2], s2[3]));
                float sl, sh; unpk(ss, sl, sh);
                sum = warp_sum(sl + sh);
            }
        }

        // packed sum of squares + warp reduction
        u64 sq2 = mul2(s2[0], s2[0]);
        sq2 = fma2(s2[1], s2[1], sq2);
        sq2 = fma2(s2[2], s2[2], sq2);
        sq2 = fma2(s2[3], s2[3], sq2);
        float sql, sqh; unpk(sq2, sql, sqh);
        float sq = warp_sum(sql + sqh);

        float mu  = sum * (1.f / 256.f);
        float var = fmaf(sq, 1.f / 256.f, -mu * mu);
        float rs  = rsqrtf(var + EPSF);
        float nm  = -mu * rs;
        u64 rs2 = pk(rs, rs), nm2 = pk(nm, nm);

        u64 accm = 0, acce = 0;
#pragma unroll
        for (int p = 0; p < 4; p++) {
            u64 t2 = fma2(s2[p], rs2, nm2);
            u64 h2 = fma2(t2, g2[p], be2[p]);     // hn * log2(e)
            float hl, hh; unpk(h2, hl, hh);
            float e0 = ex2f(fminf(hl, 0.f));
            float e1 = ex2f(fminf(hh, 0.f));
            float m0 = fmaxf(hl, 0.f);
            float m1 = fmaxf(hh, 0.f);
            accm = fma2(pk(m0, m1), wm2[p], accm);
            acce = fma2(pk(e0, e1), we2[p], acce);
        }
        float aml, amh, ael, aeh;
        unpk(accm, aml, amh); unpk(acce, ael, aeh);
        float acc = warp_sum((aml + amh) + (ael + aeh));
        if (lane == 0) sOut[cidx] = acc + CADD;
    }
    __syncthreads();
    out[(i0 + (t >> 4)) * NN + j0 + (t & 15)] = sOut[t];
}

// ---------------------------------------------------------------------------
extern "C" void kernel_launch(void* const* d_in, const int* in_sizes, int n_in,
                              void* d_out, int out_size)
{
    const float* xl    = (const float*)d_in[0];
    const float* xr    = (const float*)d_in[1];
    const float* W1    = (const float*)d_in[2];
    const float* b1    = (const float*)d_in[3];
    const float* gamma = (const float*)d_in[4];
    const float* beta  = (const float*)d_in[5];
    const float* W2    = (const float*)d_in[6];
    const float* b2    = (const float*)d_in[7];
    float* out = (float*)d_out;

    dim3 gpre(8, 12, 2);
    gemm_pre_kernel<<<gpre, 256>>>(xl, xr, W1);
    combine_kernel<<<NN, 256>>>(b1);
    dim3 grid(NN / 16, NN / 16);
    pair_main_kernel<<<grid, 256>>>(gamma, beta, W2, b2, out);
}

// round 5
// speedup vs baseline: 1.3261x; 1.3261x over previous
#include <cuda_runtime.h>

#define NN 512
#define CC 64
#define HH 256
#define EPSF 1e-5f

typedef unsigned long long u64;

// ---------------- packed f32x2 helpers (sm_100+) ----------------
__device__ __forceinline__ u64 pk(float lo, float hi) {
    u64 r; asm("mov.b64 %0,{%1,%2};" : "=l"(r) : "f"(lo), "f"(hi)); return r;
}
__device__ __forceinline__ void unpk(u64 v, float& lo, float& hi) {
    asm("mov.b64 {%0,%1},%2;" : "=f"(lo), "=f"(hi) : "l"(v));
}
__device__ __forceinline__ u64 add2(u64 a, u64 b) {
    u64 r; asm("add.rn.f32x2 %0,%1,%2;" : "=l"(r) : "l"(a), "l"(b)); return r;
}
__device__ __forceinline__ u64 fma2(u64 a, u64 b, u64 c) {
    u64 r; asm("fma.rn.f32x2 %0,%1,%2,%3;" : "=l"(r) : "l"(a), "l"(b), "l"(c)); return r;
}
__device__ __forceinline__ float ex2f(float x) {
    float r; asm("ex2.approx.f32 %0,%1;" : "=f"(r) : "f"(x)); return r;
}
__device__ __forceinline__ float warp_sum(float x) {
#pragma unroll
    for (int off = 16; off > 0; off >>= 1)
        x += __shfl_xor_sync(0xffffffffu, x, off);
    return x;
}

// ---------------- scratch (device globals) ----------------
__device__ float g_T[2][NN][768];
__device__ float g_RA [NN*HH];
__device__ float g_RB [NN*HH];
__device__ float g_A1M[NN*HH];
__device__ float g_A2P[NN*HH];
__device__ float g_B1P[NN*HH];
__device__ float g_B2M[NN*HH];
__device__ float g_SA[NN];
__device__ float g_SB[NN];
__device__ float g_CW;          // sum of W2

// ---------------------------------------------------------------------------
// Stage 1: tiled GEMM. M=512, N=768, K=64, two batches (xl / xr).
// ---------------------------------------------------------------------------
__global__ __launch_bounds__(256) void gemm_pre_kernel(
    const float* __restrict__ xl, const float* __restrict__ xr,
    const float* __restrict__ W1)
{
    __shared__ float Xs[64][68];
    __shared__ float Ws[64][68];

    const int z  = blockIdx.z;
    const float* X = z ? xr : xl;
    const int m0 = blockIdx.x * 64;
    const int n0 = blockIdx.y * 64;
    const int sel = n0 >> 8;
    const int h0  = n0 & 255;
    const float* Wbase = W1 + ((2 * sel + z) * 64) * HH + h0;

    const int t = threadIdx.x;
    {
        int f = t & 63, i0 = t >> 6;
#pragma unroll
        for (int ii = 0; ii < 64; ii += 4)
            Xs[f][i0 + ii] = X[(m0 + i0 + ii) * CC + f];
    }
    {
        int n = t & 63, f0 = t >> 6;
#pragma unroll
        for (int ff = 0; ff < 64; ff += 4)
            Ws[f0 + ff][n] = Wbase[(f0 + ff) * HH + n];
    }
    __syncthreads();

    const int tx = t & 15, ty = t >> 4;
    float acc[4][4] = {};
#pragma unroll 16
    for (int k = 0; k < 64; k++) {
        float4 xa = *reinterpret_cast<const float4*>(&Xs[k][4 * ty]);
        float4 wb = *reinterpret_cast<const float4*>(&Ws[k][4 * tx]);
        float xr4[4] = {xa.x, xa.y, xa.z, xa.w};
        float wr4[4] = {wb.x, wb.y, wb.z, wb.w};
#pragma unroll
        for (int r = 0; r < 4; r++)
#pragma unroll
            for (int c = 0; c < 4; c++)
                acc[r][c] = fmaf(xr4[r], wr4[c], acc[r][c]);
    }
#pragma unroll
    for (int r = 0; r < 4; r++) {
        float4 v = make_float4(acc[r][0], acc[r][1], acc[r][2], acc[r][3]);
        *reinterpret_cast<float4*>(&g_T[z][m0 + 4 * ty + r][n0 + 4 * tx]) = v;
    }
}

// ---------------------------------------------------------------------------
// Stage 2: combine shifts + b1 into RA/RB (+masked parts), row sums SA/SB,
// and (block 0) the W2 total.
// ---------------------------------------------------------------------------
__global__ __launch_bounds__(256) void combine_kernel(
    const float* __restrict__ b1, const float* __restrict__ W2)
{
    __shared__ float smA[8], smB[8], smW[8];
    const int i = blockIdx.x, h = threadIdx.x;
    const int lane = h & 31, w = h >> 5;

    float a0  = g_T[0][i][h];
    float a1m = (i > 0)      ? g_T[0][i - 1][256 + h] : 0.f;
    float a2p = (i < NN - 1) ? g_T[0][i + 1][512 + h] : 0.f;
    float ra  = a0 + b1[h] + a1m + a2p;
    g_A1M[i * HH + h] = a1m;
    g_A2P[i * HH + h] = a2p;
    g_RA [i * HH + h] = ra;

    float b0  = g_T[1][i][h];
    float b1p = (i < NN - 1) ? g_T[1][i + 1][256 + h] : 0.f;
    float b2m = (i > 0)      ? g_T[1][i - 1][512 + h] : 0.f;
    float rb  = b0 + b1p + b2m;
    g_B1P[i * HH + h] = b1p;
    g_B2M[i * HH + h] = b2m;
    g_RB [i * HH + h] = rb;

    float sa = warp_sum(ra);
    float sb = warp_sum(rb);
    float sw = warp_sum((i == 0) ? W2[h] : 0.f);
    if (lane == 0) { smA[w] = sa; smB[w] = sb; smW[w] = sw; }
    __syncthreads();
    if (h == 0) {
        float ta = 0.f, tb = 0.f, tw = 0.f;
#pragma unroll
        for (int k = 0; k < 8; k++) { ta += smA[k]; tb += smB[k]; tw += smW[k]; }
        g_SA[i] = ta; g_SB[i] = tb;
        if (i == 0) g_CW = tw;
    }
}

// ---------------------------------------------------------------------------
// Stage 3: main pairwise kernel, THREAD-per-cell (2 cells/thread), no shuffles.
// Block tile: 16 i-rows x 32 j-cols. Warp w handles rows {w, w+8}, lane = j.
// Pass 1: sum of squares (serial, f32x2). Pass 2: LN+CELU+dot(W2) (serial).
// Interior formula only; border cells overwritten by fixup_kernel.
// ---------------------------------------------------------------------------
__global__ __launch_bounds__(256) void pair_tpc_kernel(
    const float* __restrict__ gamma, const float* __restrict__ beta,
    const float* __restrict__ W2, const float* __restrict__ b2,
    float* __restrict__ out)
{
    __shared__ u64 sA[16][128];     // [row][c2]          16 KB
    __shared__ u64 sB[128][33];     // [c2][j] padded     33 KB
    __shared__ u64 sG[128], sBe[128], sWm[128], sWe[128];  // 4 KB
    __shared__ float sSA[16], sSB[32];

    const int t  = threadIdx.x;
    const int i0 = blockIdx.y * 16, j0 = blockIdx.x * 32;
    const float L2E  = 1.4426950408889634f;
    const float IL2E = 0.6931471805599453f;

    // load sA (linear copy, 2048 u64)
    {
        const u64* gA = reinterpret_cast<const u64*>(g_RA) + i0 * 128;
#pragma unroll
        for (int k = 0; k < 8; k++) {
            int idx = t + 256 * k;
            sA[idx >> 7][idx & 127] = gA[idx];
        }
    }
    // load sB transposed: sB[c2][j] = RB2[(j0+j)*128 + c2]
    {
        const u64* gB = reinterpret_cast<const u64*>(g_RB) + j0 * 128;
        int j = t >> 3, part = t & 7;
#pragma unroll
        for (int k = 0; k < 16; k++) {
            int c2 = part + 8 * k;
            sB[c2][j] = gB[j * 128 + c2];
        }
    }
    // const tables
    if (t < 128) {
        float2 gv = reinterpret_cast<const float2*>(gamma)[t];
        float2 bv = reinterpret_cast<const float2*>(beta)[t];
        float2 wv = reinterpret_cast<const float2*>(W2)[t];
        sG [t] = pk(gv.x * L2E, gv.y * L2E);
        sBe[t] = pk(bv.x * L2E, bv.y * L2E);
        sWm[t] = pk(wv.x * IL2E, wv.y * IL2E);
        sWe[t] = pk(wv.x, wv.y);
    } else if (t < 144) {
        sSA[t - 128] = g_SA[i0 + t - 128];
    } else if (t < 176) {
        sSB[t - 144] = g_SB[j0 + t - 144];
    }
    const float CADD = b2[0] - g_CW;
    __syncthreads();

    const int lane = t & 31, w = t >> 5;
    const int ra = w, rb = w + 8;

    // ---- pass 1: sum of squares for both cells ----
    u64 sqa0 = 0, sqa1 = 0, sqb0 = 0, sqb1 = 0;
#pragma unroll 4
    for (int c2 = 0; c2 < 128; c2 += 2) {
        u64 bv0 = sB[c2][lane], bv1 = sB[c2 + 1][lane];
        u64 s00 = add2(sA[ra][c2], bv0);
        u64 s01 = add2(sA[ra][c2 + 1], bv1);
        u64 s10 = add2(sA[rb][c2], bv0);
        u64 s11 = add2(sA[rb][c2 + 1], bv1);
        sqa0 = fma2(s00, s00, sqa0);
        sqa1 = fma2(s01, s01, sqa1);
        sqb0 = fma2(s10, s10, sqb0);
        sqb1 = fma2(s11, s11, sqb1);
    }
    float q0l, q0h, q1l, q1h;
    unpk(add2(sqa0, sqa1), q0l, q0h);
    unpk(add2(sqb0, sqb1), q1l, q1h);
    float sqA = q0l + q0h, sqB = q1l + q1h;

    float sumA = sSA[ra] + sSB[lane];
    float sumB = sSA[rb] + sSB[lane];
    float muA = sumA * (1.f / 256.f), muB = sumB * (1.f / 256.f);
    float rsA = rsqrtf(fmaf(sqA, 1.f / 256.f, -muA * muA) + EPSF);
    float rsB = rsqrtf(fmaf(sqB, 1.f / 256.f, -muB * muB) + EPSF);
    u64 rsA2 = pk(rsA, rsA), nmA2 = pk(-muA * rsA, -muA * rsA);
    u64 rsB2 = pk(rsB, rsB), nmB2 = pk(-muB * rsB, -muB * rsB);

    // ---- pass 2: CELU (log2e domain) + dot(W2) ----
    u64 am0 = 0, ae0 = 0, am1 = 0, ae1 = 0;
#pragma unroll 2
    for (int c2 = 0; c2 < 128; c2++) {
        u64 bv = sB[c2][lane];
        u64 gg = sG[c2], be = sBe[c2], wm = sWm[c2], we = sWe[c2];

        u64 s0 = add2(sA[ra][c2], bv);
        u64 h0 = fma2(fma2(s0, rsA2, nmA2), gg, be);
        float h0l, h0h; unpk(h0, h0l, h0h);
        float e0l = ex2f(fminf(h0l, 0.f));
        float e0h = ex2f(fminf(h0h, 0.f));
        float m0l = fmaxf(h0l, 0.f);
        float m0h = fmaxf(h0h, 0.f);
        am0 = fma2(pk(m0l, m0h), wm, am0);
        ae0 = fma2(pk(e0l, e0h), we, ae0);

        u64 s1 = add2(sA[rb][c2], bv);
        u64 h1 = fma2(fma2(s1, rsB2, nmB2), gg, be);
        float h1l, h1h; unpk(h1, h1l, h1h);
        float e1l = ex2f(fminf(h1l, 0.f));
        float e1h = ex2f(fminf(h1h, 0.f));
        float m1l = fmaxf(h1l, 0.f);
        float m1h = fmaxf(h1h, 0.f);
        am1 = fma2(pk(m1l, m1h), wm, am1);
        ae1 = fma2(pk(e1l, e1h), we, ae1);
    }
    float x0, x1, y0, y1;
    unpk(add2(am0, ae0), x0, x1);
    unpk(add2(am1, ae1), y0, y1);
    out[(i0 + ra) * NN + j0 + lane] = (x0 + x1) + CADD;
    out[(i0 + rb) * NN + j0 + lane] = (y0 + y1) + CADD;
}

// ---------------------------------------------------------------------------
// Stage 4: border fixup, warp-per-cell, vectorized loads.
// s = RA+RB - [i=0]B1P[j] - [i=511]B2M[j] - [j=0]A2P[i] - [j=511]A1M[i]
// ---------------------------------------------------------------------------
__global__ __launch_bounds__(256) void fixup_kernel(
    const float* __restrict__ gamma, const float* __restrict__ beta,
    const float* __restrict__ W2, const float* __restrict__ b2,
    float* __restrict__ out)
{
    const int gw   = (blockIdx.x * 256 + threadIdx.x) >> 5;  // 0..2047
    const int lane = threadIdx.x & 31;
    const int side = gw >> 9, pos = gw & 511;
    int i, j;
    if      (side == 0) { i = 0;      j = pos; }
    else if (side == 1) { i = NN - 1; j = pos; }
    else if (side == 2) { i = pos;    j = 0; }
    else                { i = pos;    j = NN - 1; }

    const bool mi0 = (i == 0), mi1 = (i == NN - 1);
    const bool mj0 = (j == 0), mj1 = (j == NN - 1);
    const float4 z4 = make_float4(0.f, 0.f, 0.f, 0.f);

    const float4* RA4 = reinterpret_cast<const float4*>(g_RA)  + i * 64;
    const float4* RB4 = reinterpret_cast<const float4*>(g_RB)  + j * 64;
    const float4* BP4 = reinterpret_cast<const float4*>(g_B1P) + j * 64;
    const float4* BM4 = reinterpret_cast<const float4*>(g_B2M) + j * 64;
    const float4* AP4 = reinterpret_cast<const float4*>(g_A2P) + i * 64;
    const float4* AM4 = reinterpret_cast<const float4*>(g_A1M) + i * 64;

    float s[8], gm[8], bt[8], w2r[8];
#pragma unroll
    for (int half = 0; half < 2; half++) {
        int idx = lane + 32 * half;
        float4 ra = RA4[idx];
        float4 rb = RB4[idx];
        float4 c1 = mi0 ? BP4[idx] : z4;
        float4 c2 = mi1 ? BM4[idx] : z4;
        float4 c3 = mj0 ? AP4[idx] : z4;
        float4 c4 = mj1 ? AM4[idx] : z4;
        int o = 4 * half;
        s[o + 0] = ra.x + rb.x - c1.x - c2.x - c3.x - c4.x;
        s[o + 1] = ra.y + rb.y - c1.y - c2.y - c3.y - c4.y;
        s[o + 2] = ra.z + rb.z - c1.z - c2.z - c3.z - c4.z;
        s[o + 3] = ra.w + rb.w - c1.w - c2.w - c3.w - c4.w;
        float4 gv = reinterpret_cast<const float4*>(gamma)[idx + 32 * half * 0];
        // channels owned by this lane: 4*lane.. (half 0), 128+4*lane.. (half 1)
        gv = reinterpret_cast<const float4*>(gamma)[idx];
        float4 bv = reinterpret_cast<const float4*>(beta )[idx];
        float4 wv = reinterpret_cast<const float4*>(W2   )[idx];
        gm[o] = gv.x; gm[o+1] = gv.y; gm[o+2] = gv.z; gm[o+3] = gv.w;
        bt[o] = bv.x; bt[o+1] = bv.y; bt[o+2] = bv.z; bt[o+3] = bv.w;
        w2r[o] = wv.x; w2r[o+1] = wv.y; w2r[o+2] = wv.z; w2r[o+3] = wv.w;
    }

    float sum = ((s[0] + s[1]) + (s[2] + s[3])) + ((s[4] + s[5]) + (s[6] + s[7]));
    float sq  = fmaf(s[0], s[0], s[1] * s[1]);
    sq = fmaf(s[2], s[2], fmaf(s[3], s[3], sq));
    sq = fmaf(s[4], s[4], sq);
    sq = fmaf(s[5], s[5], sq);
    sq = fmaf(s[6], s[6], fmaf(s[7], s[7], sq));
    sum = warp_sum(sum);
    sq  = warp_sum(sq);

    float mu  = sum * (1.f / 256.f);
    float var = fmaf(sq, 1.f / 256.f, -mu * mu);
    float rs  = rsqrtf(var + EPSF);
    float nm  = -mu * rs;
    float acc = 0.f;
#pragma unroll
    for (int k = 0; k < 8; k++) {
        float hn = fmaf(fmaf(s[k], rs, nm), gm[k], bt[k]);
        float e  = __expf(fminf(hn, 0.f)) - 1.f;
        float v  = fmaxf(hn, 0.f) + e;
        acc = fmaf(v, w2r[k], acc);
    }
    acc = warp_sum(acc);
    if (lane == 0) out[i * NN + j] = acc + b2[0];
}

// ---------------------------------------------------------------------------
extern "C" void kernel_launch(void* const* d_in, const int* in_sizes, int n_in,
                              void* d_out, int out_size)
{
    const float* xl    = (const float*)d_in[0];
    const float* xr    = (const float*)d_in[1];
    const float* W1    = (const float*)d_in[2];
    const float* b1    = (const float*)d_in[3];
    const float* gamma = (const float*)d_in[4];
    const float* beta  = (const float*)d_in[5];
    const float* W2    = (const float*)d_in[6];
    const float* b2    = (const float*)d_in[7];
    float* out = (float*)d_out;

    dim3 gpre(8, 12, 2);
    gemm_pre_kernel<<<gpre, 256>>>(xl, xr, W1);
    combine_kernel<<<NN, 256>>>(b1, W2);
    dim3 grid(NN / 32, NN / 16);
    pair_tpc_kernel<<<grid, 256>>>(gamma, beta, W2, b2, out);
    fixup_kernel<<<(4 * NN * 32) / 256, 256>>>(gamma, beta, W2, b2, out);
}

// round 6
// speedup vs baseline: 1.4175x; 1.0689x over previous
#include <cuda_runtime.h>

#define NN 512
#define CC 64
#define HH 256
#define EPSF 1e-5f

typedef unsigned long long u64;

// ---------------- packed f32x2 helpers (sm_100+) ----------------
__device__ __forceinline__ u64 pk(float lo, float hi) {
    u64 r; asm("mov.b64 %0,{%1,%2};" : "=l"(r) : "f"(lo), "f"(hi)); return r;
}
__device__ __forceinline__ void unpk(u64 v, float& lo, float& hi) {
    asm("mov.b64 {%0,%1},%2;" : "=f"(lo), "=f"(hi) : "l"(v));
}
__device__ __forceinline__ u64 add2(u64 a, u64 b) {
    u64 r; asm("add.rn.f32x2 %0,%1,%2;" : "=l"(r) : "l"(a), "l"(b)); return r;
}
__device__ __forceinline__ u64 fma2(u64 a, u64 b, u64 c) {
    u64 r; asm("fma.rn.f32x2 %0,%1,%2,%3;" : "=l"(r) : "l"(a), "l"(b), "l"(c)); return r;
}
__device__ __forceinline__ float ex2f(float x) {
    float r; asm("ex2.approx.f32 %0,%1;" : "=f"(r) : "f"(x)); return r;
}
__device__ __forceinline__ float warp_sum(float x) {
#pragma unroll
    for (int off = 16; off > 0; off >>= 1)
        x += __shfl_xor_sync(0xffffffffu, x, off);
    return x;
}

// ---------------- scratch (device globals) ----------------
__device__ float g_T[2][NN][768];
__device__ float g_RA [NN*HH];
__device__ float g_RB [NN*HH];
__device__ float g_A1M[NN*HH];
__device__ float g_A2P[NN*HH];
__device__ float g_B1P[NN*HH];
__device__ float g_B2M[NN*HH];
__device__ float g_SA[NN];
__device__ float g_SB[NN];
__device__ float g_CW;

// ---------------------------------------------------------------------------
// Stage 1: tiled GEMM. M=512, N=768, K=64, two batches. 32x64 tiles, grid=384.
// ---------------------------------------------------------------------------
__global__ __launch_bounds__(256) void gemm_pre_kernel(
    const float* __restrict__ xl, const float* __restrict__ xr,
    const float* __restrict__ W1)
{
    __shared__ float Xs[64][36];   // [k][m], padded
    __shared__ float Ws[64][68];   // [k][n], padded

    const int z  = blockIdx.z;
    const float* X = z ? xr : xl;
    const int m0 = blockIdx.x * 32;
    const int n0 = blockIdx.y * 64;
    const int sel = n0 >> 8;
    const int h0  = n0 & 255;
    const float* Wbase = W1 + ((2 * sel + z) * 64) * HH + h0;

    const int t = threadIdx.x;
    {
        int f = t & 63, i0 = t >> 6;     // i0 in 0..3
#pragma unroll
        for (int ii = 0; ii < 32; ii += 4)
            Xs[f][i0 + ii] = X[(m0 + i0 + ii) * CC + f];
    }
    {
        int n = t & 63, f0 = t >> 6;
#pragma unroll
        for (int ff = 0; ff < 64; ff += 4)
            Ws[f0 + ff][n] = Wbase[(f0 + ff) * HH + n];
    }
    __syncthreads();

    const int tx = t & 15, ty = t >> 4;  // n = n0+4tx.., m = m0+2ty..
    float acc[2][4] = {};
#pragma unroll 16
    for (int k = 0; k < 64; k++) {
        float2 xa = *reinterpret_cast<const float2*>(&Xs[k][2 * ty]);
        float4 wb = *reinterpret_cast<const float4*>(&Ws[k][4 * tx]);
        float xr2[2] = {xa.x, xa.y};
        float wr4[4] = {wb.x, wb.y, wb.z, wb.w};
#pragma unroll
        for (int r = 0; r < 2; r++)
#pragma unroll
            for (int c = 0; c < 4; c++)
                acc[r][c] = fmaf(xr2[r], wr4[c], acc[r][c]);
    }
#pragma unroll
    for (int r = 0; r < 2; r++) {
        float4 v = make_float4(acc[r][0], acc[r][1], acc[r][2], acc[r][3]);
        *reinterpret_cast<float4*>(&g_T[z][m0 + 2 * ty + r][n0 + 4 * tx]) = v;
    }
}

// ---------------------------------------------------------------------------
// Stage 2: combine shifts + b1 into RA/RB (+masked parts), row sums, W2 total.
// ---------------------------------------------------------------------------
__global__ __launch_bounds__(256) void combine_kernel(
    const float* __restrict__ b1, const float* __restrict__ W2)
{
    __shared__ float smA[8], smB[8], smW[8];
    const int i = blockIdx.x, h = threadIdx.x;
    const int lane = h & 31, w = h >> 5;

    float a0  = g_T[0][i][h];
    float a1m = (i > 0)      ? g_T[0][i - 1][256 + h] : 0.f;
    float a2p = (i < NN - 1) ? g_T[0][i + 1][512 + h] : 0.f;
    float ra  = a0 + b1[h] + a1m + a2p;
    g_A1M[i * HH + h] = a1m;
    g_A2P[i * HH + h] = a2p;
    g_RA [i * HH + h] = ra;

    float b0  = g_T[1][i][h];
    float b1p = (i < NN - 1) ? g_T[1][i + 1][256 + h] : 0.f;
    float b2m = (i > 0)      ? g_T[1][i - 1][512 + h] : 0.f;
    float rb  = b0 + b1p + b2m;
    g_B1P[i * HH + h] = b1p;
    g_B2M[i * HH + h] = b2m;
    g_RB [i * HH + h] = rb;

    float sa = warp_sum(ra);
    float sb = warp_sum(rb);
    float sw = warp_sum((i == 0) ? W2[h] : 0.f);
    if (lane == 0) { smA[w] = sa; smB[w] = sb; smW[w] = sw; }
    __syncthreads();
    if (h == 0) {
        float ta = 0.f, tb = 0.f, tw = 0.f;
#pragma unroll
        for (int k = 0; k < 8; k++) { ta += smA[k]; tb += smB[k]; tw += smW[k]; }
        g_SA[i] = ta; g_SB[i] = tb;
        if (i == 0) g_CW = tw;
    }
}

// ---------------------------------------------------------------------------
// Stage 3: fused kernel. Blocks 0..255: 32x32 tile, thread = 4 cells (R=4).
// Blocks 256..287: border fixup (warp-per-cell, 8 cells/warp).
// Main tiles SKIP border stores; fixup blocks own them (no write race).
// ---------------------------------------------------------------------------
#define SA_OFF   0
#define SB_OFF   32768
#define SGB_OFF  66560
#define SW_OFF   68608
#define SSA_OFF  70656
#define SSB_OFF  70784
#define SMEM_SZ  70912

__global__ __launch_bounds__(256) void pair_fused_kernel(
    const float* __restrict__ gamma, const float* __restrict__ beta,
    const float* __restrict__ W2, const float* __restrict__ b2,
    float* __restrict__ out)
{
    const int t = threadIdx.x;
    const int lane = t & 31, w = t >> 5;

    if (blockIdx.x >= 256) {
        // ================= fixup path =================
        const int fb = blockIdx.x - 256;           // 0..31
#pragma unroll 1
        for (int c = 0; c < 8; c++) {
            const int gw = fb * 8 + w + 256 * c;   // 0..2047
            const int side = gw >> 9, pos = gw & 511;
            int i, j;
            if      (side == 0) { i = 0;      j = pos; }
            else if (side == 1) { i = NN - 1; j = pos; }
            else if (side == 2) { i = pos;    j = 0; }
            else                { i = pos;    j = NN - 1; }

            const bool mi0 = (i == 0), mi1 = (i == NN - 1);
            const bool mj0 = (j == 0), mj1 = (j == NN - 1);
            const float4 z4 = make_float4(0.f, 0.f, 0.f, 0.f);

            const float4* RA4 = reinterpret_cast<const float4*>(g_RA)  + i * 64;
            const float4* RB4 = reinterpret_cast<const float4*>(g_RB)  + j * 64;
            const float4* BP4 = reinterpret_cast<const float4*>(g_B1P) + j * 64;
            const float4* BM4 = reinterpret_cast<const float4*>(g_B2M) + j * 64;
            const float4* AP4 = reinterpret_cast<const float4*>(g_A2P) + i * 64;
            const float4* AM4 = reinterpret_cast<const float4*>(g_A1M) + i * 64;

            float s[8], gm[8], bt[8], w2r[8];
#pragma unroll
            for (int half = 0; half < 2; half++) {
                int idx = lane + 32 * half;
                float4 ra = RA4[idx];
                float4 rb = RB4[idx];
                float4 c1 = mi0 ? BP4[idx] : z4;
                float4 c2 = mi1 ? BM4[idx] : z4;
                float4 c3 = mj0 ? AP4[idx] : z4;
                float4 c4 = mj1 ? AM4[idx] : z4;
                int o = 4 * half;
                s[o + 0] = ra.x + rb.x - c1.x - c2.x - c3.x - c4.x;
                s[o + 1] = ra.y + rb.y - c1.y - c2.y - c3.y - c4.y;
                s[o + 2] = ra.z + rb.z - c1.z - c2.z - c3.z - c4.z;
                s[o + 3] = ra.w + rb.w - c1.w - c2.w - c3.w - c4.w;
                float4 gv = reinterpret_cast<const float4*>(gamma)[idx];
                float4 bv = reinterpret_cast<const float4*>(beta )[idx];
                float4 wv = reinterpret_cast<const float4*>(W2   )[idx];
                gm[o] = gv.x; gm[o+1] = gv.y; gm[o+2] = gv.z; gm[o+3] = gv.w;
                bt[o] = bv.x; bt[o+1] = bv.y; bt[o+2] = bv.z; bt[o+3] = bv.w;
                w2r[o] = wv.x; w2r[o+1] = wv.y; w2r[o+2] = wv.z; w2r[o+3] = wv.w;
            }

            float sum = ((s[0] + s[1]) + (s[2] + s[3])) + ((s[4] + s[5]) + (s[6] + s[7]));
            float sq  = fmaf(s[0], s[0], s[1] * s[1]);
            sq = fmaf(s[2], s[2], fmaf(s[3], s[3], sq));
            sq = fmaf(s[4], s[4], sq);
            sq = fmaf(s[5], s[5], sq);
            sq = fmaf(s[6], s[6], fmaf(s[7], s[7], sq));
            sum = warp_sum(sum);
            sq  = warp_sum(sq);

            float mu  = sum * (1.f / 256.f);
            float var = fmaf(sq, 1.f / 256.f, -mu * mu);
            float rs  = rsqrtf(var + EPSF);
            float nm  = -mu * rs;
            float acc = 0.f;
#pragma unroll
            for (int k = 0; k < 8; k++) {
                float hn = fmaf(fmaf(s[k], rs, nm), gm[k], bt[k]);
                float e  = __expf(fminf(hn, 0.f)) - 1.f;
                float v  = fmaxf(hn, 0.f) + e;
                acc = fmaf(v, w2r[k], acc);
            }
            acc = warp_sum(acc);
            if (lane == 0) out[i * NN + j] = acc + b2[0];
        }
        return;
    }

    // ================= main tile path =================
    extern __shared__ __align__(16) char smem_raw[];
    u64 (*sA)[128] = reinterpret_cast<u64(*)[128]>(smem_raw + SA_OFF);
    u64 (*sB)[33]  = reinterpret_cast<u64(*)[33]>(smem_raw + SB_OFF);
    u64 (*sGB)[2]  = reinterpret_cast<u64(*)[2]>(smem_raw + SGB_OFF);
    u64 (*sW)[2]   = reinterpret_cast<u64(*)[2]>(smem_raw + SW_OFF);
    float* sSA = reinterpret_cast<float*>(smem_raw + SSA_OFF);
    float* sSB = reinterpret_cast<float*>(smem_raw + SSB_OFF);

    const int i0 = (blockIdx.x >> 4) * 32, j0 = (blockIdx.x & 15) * 32;
    const float L2E  = 1.4426950408889634f;
    const float IL2E = 0.6931471805599453f;

    {   // sA: 32 rows x 128 u64, linear copy
        const u64* gA = reinterpret_cast<const u64*>(g_RA) + i0 * 128;
#pragma unroll
        for (int k = 0; k < 16; k++) {
            int idx = t + 256 * k;
            sA[idx >> 7][idx & 127] = gA[idx];
        }
    }
    {   // sB transposed: sB[c2][j]
        const u64* gB = reinterpret_cast<const u64*>(g_RB) + j0 * 128;
        int j = t >> 3, part = t & 7;
#pragma unroll
        for (int k = 0; k < 16; k++) {
            int c2 = part + 8 * k;
            sB[c2][j] = gB[j * 128 + c2];
        }
    }
    if (t < 128) {
        float2 gv = reinterpret_cast<const float2*>(gamma)[t];
        float2 bv = reinterpret_cast<const float2*>(beta)[t];
        float2 wv = reinterpret_cast<const float2*>(W2)[t];
        sGB[t][0] = pk(gv.x * L2E, gv.y * L2E);
        sGB[t][1] = pk(bv.x * L2E, bv.y * L2E);
        sW [t][0] = pk(wv.x * IL2E, wv.y * IL2E);
        sW [t][1] = pk(wv.x, wv.y);
    } else if (t < 160) {
        sSA[t - 128] = g_SA[i0 + t - 128];
    } else if (t < 192) {
        sSB[t - 160] = g_SB[j0 + t - 160];
    }
    const float CADD = b2[0] - g_CW;
    __syncthreads();

    const int r0 = 4 * w;

    // ---- pass 1: sum of squares for 4 rows ----
    u64 sq[4] = {0, 0, 0, 0};
#pragma unroll 4
    for (int c2 = 0; c2 < 128; c2++) {
        u64 bv = sB[c2][lane];
#pragma unroll
        for (int r = 0; r < 4; r++) {
            u64 s = add2(sA[r0 + r][c2], bv);
            sq[r] = fma2(s, s, sq[r]);
        }
    }
    u64 rs2[4], nm2[4];
#pragma unroll
    for (int r = 0; r < 4; r++) {
        float ql, qh; unpk(sq[r], ql, qh);
        float sum = sSA[r0 + r] + sSB[lane];
        float mu  = sum * (1.f / 256.f);
        float var = fmaf(ql + qh, 1.f / 256.f, -mu * mu);
        float rs  = rsqrtf(var + EPSF);
        rs2[r] = pk(rs, rs);
        float nm = -mu * rs;
        nm2[r] = pk(nm, nm);
    }

    // ---- pass 2: CELU (log2e domain) + dot(W2) ----
    u64 am[4] = {0, 0, 0, 0}, ae[4] = {0, 0, 0, 0};
#pragma unroll 2
    for (int c2 = 0; c2 < 128; c2++) {
        u64 bv = sB[c2][lane];
        ulonglong2 gb = *reinterpret_cast<const ulonglong2*>(sGB[c2]);
        ulonglong2 wv = *reinterpret_cast<const ulonglong2*>(sW[c2]);
#pragma unroll
        for (int r = 0; r < 4; r++) {
            u64 s = add2(sA[r0 + r][c2], bv);
            u64 h = fma2(fma2(s, rs2[r], nm2[r]), gb.x, gb.y);
            float hl, hh; unpk(h, hl, hh);
            float el = ex2f(fminf(hl, 0.f));
            float eh = ex2f(fminf(hh, 0.f));
            float ml = fmaxf(hl, 0.f);
            float mh = fmaxf(hh, 0.f);
            am[r] = fma2(pk(ml, mh), wv.x, am[r]);
            ae[r] = fma2(pk(el, eh), wv.y, ae[r]);
        }
    }

    const int gj = j0 + lane;
    const bool jint = (gj != 0) && (gj != NN - 1);
#pragma unroll
    for (int r = 0; r < 4; r++) {
        int gi = i0 + r0 + r;
        if (jint && gi != 0 && gi != NN - 1) {
            float a, b; unpk(add2(am[r], ae[r]), a, b);
            out[gi * NN + gj] = (a + b) + CADD;
        }
    }
}

// ---------------------------------------------------------------------------
extern "C" void kernel_launch(void* const* d_in, const int* in_sizes, int n_in,
                              void* d_out, int out_size)
{
    const float* xl    = (const float*)d_in[0];
    const float* xr    = (const float*)d_in[1];
    const float* W1    = (const float*)d_in[2];
    const float* b1    = (const float*)d_in[3];
    const float* gamma = (const float*)d_in[4];
    const float* beta  = (const float*)d_in[5];
    const float* W2    = (const float*)d_in[6];
    const float* b2    = (const float*)d_in[7];
    float* out = (float*)d_out;

    static bool attr_set = false;
    if (!attr_set) {
        cudaFuncSetAttribute(pair_fused_kernel,
                             cudaFuncAttributeMaxDynamicSharedMemorySize, SMEM_SZ);
        attr_set = true;
    }

    dim3 gpre(16, 12, 2);
    gemm_pre_kernel<<<gpre, 256>>>(xl, xr, W1);
    combine_kernel<<<NN, 256>>>(b1, W2);
    pair_fused_kernel<<<256 + 32, 256, SMEM_SZ>>>(gamma, beta, W2, b2, out);
}

// round 8
// speedup vs baseline: 1.4184x; 1.0006x over previous
#include <cuda_runtime.h>

#define NN 512
#define CC 64
#define HH 256
#define EPSF 1e-5f

typedef unsigned long long u64;

// ---------------- packed f32x2 helpers (verified on sm_103a) ----------------
__device__ __forceinline__ u64 pk(float lo, float hi) {
    u64 r; asm("mov.b64 %0,{%1,%2};" : "=l"(r) : "f"(lo), "f"(hi)); return r;
}
__device__ __forceinline__ void unpk(u64 v, float& lo, float& hi) {
    asm("mov.b64 {%0,%1},%2;" : "=f"(lo), "=f"(hi) : "l"(v));
}
__device__ __forceinline__ u64 add2(u64 a, u64 b) {
    u64 r; asm("add.rn.f32x2 %0,%1,%2;" : "=l"(r) : "l"(a), "l"(b)); return r;
}
__device__ __forceinline__ u64 fma2(u64 a, u64 b, u64 c) {
    u64 r; asm("fma.rn.f32x2 %0,%1,%2,%3;" : "=l"(r) : "l"(a), "l"(b), "l"(c)); return r;
}
__device__ __forceinline__ float ex2f(float x) {
    float r; asm("ex2.approx.f32 %0,%1;" : "=f"(r) : "f"(x)); return r;
}
__device__ __forceinline__ float warp_sum(float x) {
#pragma unroll
    for (int off = 16; off > 0; off >>= 1)
        x += __shfl_xor_sync(0xffffffffu, x, off);
    return x;
}

// ---------------- scratch (device globals) ----------------
__device__ float g_T[2][NN][768];
__device__ float g_RA [NN*HH];
__device__ float g_RB [NN*HH];
__device__ float g_A1M[NN*HH];
__device__ float g_A2P[NN*HH];
__device__ float g_B1P[NN*HH];
__device__ float g_B2M[NN*HH];
__device__ float g_SA[NN];
__device__ float g_SB[NN];
__device__ float g_QA[NN];
__device__ float g_QB[NN];
__device__ float g_CW;

// ---------------------------------------------------------------------------
// Stage 1: GEMM, 32x32 tiles, 128 threads, f32x2 microtile 2m x 4n. Grid 768.
// ---------------------------------------------------------------------------
__global__ __launch_bounds__(128) void gemm_pre_kernel(
    const float* __restrict__ xl, const float* __restrict__ xr,
    const float* __restrict__ W1)
{
    __shared__ float Xs[64][36];   // [k][m]
    __shared__ float Ws[64][36];   // [k][n]

    const int z  = blockIdx.z;
    const float* X = z ? xr : xl;
    const int m0 = blockIdx.x * 32;
    const int n0 = blockIdx.y * 32;
    const int sel = n0 >> 8;
    const int h0  = n0 & 255;
    const float* Wbase = W1 + ((2 * sel + z) * 64) * HH + h0;

    const int t = threadIdx.x;
    {   // Xs[f][i] = X[(m0+i)*64 + f]
        int f = t & 63, i2 = t >> 6;          // i2: 0..1
#pragma unroll
        for (int ii = 0; ii < 32; ii += 2)
            Xs[f][i2 + ii] = X[(m0 + i2 + ii) * CC + f];
    }
    {   // Ws[f][n] = Wbase[f*HH + n]
        int n = t & 31, f0 = t >> 5;          // f0: 0..3
#pragma unroll
        for (int ff = 0; ff < 64; ff += 4)
            Ws[f0 + ff][n] = Wbase[(f0 + ff) * HH + n];
    }
    __syncthreads();

    const int tx = t & 7, ty = t >> 3;        // n = n0+4tx, m = m0+2ty
    u64 acc[2][2] = {};
#pragma unroll 16
    for (int k = 0; k < 64; k++) {
        float2 xa = *reinterpret_cast<const float2*>(&Xs[k][2 * ty]);
        ulonglong2 wb = *reinterpret_cast<const ulonglong2*>(&Ws[k][4 * tx]);
        u64 x0 = pk(xa.x, xa.x), x1 = pk(xa.y, xa.y);
        acc[0][0] = fma2(x0, wb.x, acc[0][0]);
        acc[0][1] = fma2(x0, wb.y, acc[0][1]);
        acc[1][0] = fma2(x1, wb.x, acc[1][0]);
        acc[1][1] = fma2(x1, wb.y, acc[1][1]);
    }
#pragma unroll
    for (int r = 0; r < 2; r++) {
        float a, b, c, d;
        unpk(acc[r][0], a, b);
        unpk(acc[r][1], c, d);
        *reinterpret_cast<float4*>(&g_T[z][m0 + 2 * ty + r][n0 + 4 * tx]) =
            make_float4(a, b, c, d);
    }
}

// ---------------------------------------------------------------------------
// Stage 2: combine shifts + b1 into RA/RB (+masked parts), row sums SA/SB,
// row sums-of-squares QA/QB, W2 total.
// ---------------------------------------------------------------------------
__global__ __launch_bounds__(256) void combine_kernel(
    const float* __restrict__ b1, const float* __restrict__ W2)
{
    __shared__ float smA[8], smB[8], smW[8], smQA[8], smQB[8];
    const int i = blockIdx.x, h = threadIdx.x;
    const int lane = h & 31, w = h >> 5;

    float a0  = g_T[0][i][h];
    float a1m = (i > 0)      ? g_T[0][i - 1][256 + h] : 0.f;
    float a2p = (i < NN - 1) ? g_T[0][i + 1][512 + h] : 0.f;
    float ra  = a0 + b1[h] + a1m + a2p;
    g_A1M[i * HH + h] = a1m;
    g_A2P[i * HH + h] = a2p;
    g_RA [i * HH + h] = ra;

    float b0  = g_T[1][i][h];
    float b1p = (i < NN - 1) ? g_T[1][i + 1][256 + h] : 0.f;
    float b2m = (i > 0)      ? g_T[1][i - 1][512 + h] : 0.f;
    float rb  = b0 + b1p + b2m;
    g_B1P[i * HH + h] = b1p;
    g_B2M[i * HH + h] = b2m;
    g_RB [i * HH + h] = rb;

    float sa = warp_sum(ra);
    float sb = warp_sum(rb);
    float qa = warp_sum(ra * ra);
    float qb = warp_sum(rb * rb);
    float sw = warp_sum((i == 0) ? W2[h] : 0.f);
    if (lane == 0) { smA[w] = sa; smB[w] = sb; smQA[w] = qa; smQB[w] = qb; smW[w] = sw; }
    __syncthreads();
    if (h == 0) {
        float ta = 0.f, tb = 0.f, tqa = 0.f, tqb = 0.f, tw = 0.f;
#pragma unroll
        for (int k = 0; k < 8; k++) {
            ta += smA[k]; tb += smB[k]; tqa += smQA[k]; tqb += smQB[k]; tw += smW[k];
        }
        g_SA[i] = ta; g_SB[i] = tb;
        g_QA[i] = tqa; g_QB[i] = tqb;
        if (i == 0) g_CW = tw;
    }
}

// ---------------------------------------------------------------------------
// Stage 3: fused kernel. Blocks 0..255: 32x32 tile, R=4 rows/thread.
//   pass1: cross-dot X = sum RA*RB (packed); sq = QA + QB + 2X.
//   pass2: LN + CELU (log2e domain) + dot(W2).
// Blocks 256..287: border fixup. Main tiles skip border stores.
// ---------------------------------------------------------------------------
#define SA_OFF   0
#define SB_OFF   32768
#define SGB_OFF  66560
#define SW_OFF   68608
#define SSA_OFF  70656
#define SSB_OFF  70784
#define SQA_OFF  70912
#define SQB_OFF  71040
#define SMEM_SZ  71168

__global__ __launch_bounds__(256) void pair_fused_kernel(
    const float* __restrict__ gamma, const float* __restrict__ beta,
    const float* __restrict__ W2, const float* __restrict__ b2,
    float* __restrict__ out)
{
    const int t = threadIdx.x;
    const int lane = t & 31, w = t >> 5;

    if (blockIdx.x >= 256) {
        // ================= fixup path =================
        const int fb = blockIdx.x - 256;
#pragma unroll 1
        for (int c = 0; c < 8; c++) {
            const int gw = fb * 8 + w + 256 * c;
            const int side = gw >> 9, pos = gw & 511;
            int i, j;
            if      (side == 0) { i = 0;      j = pos; }
            else if (side == 1) { i = NN - 1; j = pos; }
            else if (side == 2) { i = pos;    j = 0; }
            else                { i = pos;    j = NN - 1; }

            const bool mi0 = (i == 0), mi1 = (i == NN - 1);
            const bool mj0 = (j == 0), mj1 = (j == NN - 1);
            const float4 z4 = make_float4(0.f, 0.f, 0.f, 0.f);

            const float4* RA4 = reinterpret_cast<const float4*>(g_RA)  + i * 64;
            const float4* RB4 = reinterpret_cast<const float4*>(g_RB)  + j * 64;
            const float4* BP4 = reinterpret_cast<const float4*>(g_B1P) + j * 64;
            const float4* BM4 = reinterpret_cast<const float4*>(g_B2M) + j * 64;
            const float4* AP4 = reinterpret_cast<const float4*>(g_A2P) + i * 64;
            const float4* AM4 = reinterpret_cast<const float4*>(g_A1M) + i * 64;

            float s[8], gm[8], bt[8], w2r[8];
#pragma unroll
            for (int half = 0; half < 2; half++) {
                int idx = lane + 32 * half;
                float4 ra = RA4[idx];
                float4 rb = RB4[idx];
                float4 c1 = mi0 ? BP4[idx] : z4;
                float4 c2 = mi1 ? BM4[idx] : z4;
                float4 c3 = mj0 ? AP4[idx] : z4;
                float4 c4 = mj1 ? AM4[idx] : z4;
                int o = 4 * half;
                s[o + 0] = ra.x + rb.x - c1.x - c2.x - c3.x - c4.x;
                s[o + 1] = ra.y + rb.y - c1.y - c2.y - c3.y - c4.y;
                s[o + 2] = ra.z + rb.z - c1.z - c2.z - c3.z - c4.z;
                s[o + 3] = ra.w + rb.w - c1.w - c2.w - c3.w - c4.w;
                float4 gv = reinterpret_cast<const float4*>(gamma)[idx];
                float4 bv = reinterpret_cast<const float4*>(beta )[idx];
                float4 wv = reinterpret_cast<const float4*>(W2   )[idx];
                gm[o] = gv.x; gm[o+1] = gv.y; gm[o+2] = gv.z; gm[o+3] = gv.w;
                bt[o] = bv.x; bt[o+1] = bv.y; bt[o+2] = bv.z; bt[o+3] = bv.w;
                w2r[o] = wv.x; w2r[o+1] = wv.y; w2r[o+2] = wv.z; w2r[o+3] = wv.w;
            }

            float sum = ((s[0] + s[1]) + (s[2] + s[3])) + ((s[4] + s[5]) + (s[6] + s[7]));
            float sq  = fmaf(s[0], s[0], s[1] * s[1]);
            sq = fmaf(s[2], s[2], fmaf(s[3], s[3], sq));
            sq = fmaf(s[4], s[4], sq);
            sq = fmaf(s[5], s[5], sq);
            sq = fmaf(s[6], s[6], fmaf(s[7], s[7], sq));
            sum = warp_sum(sum);
            sq  = warp_sum(sq);

            float mu  = sum * (1.f / 256.f);
            float var = fmaf(sq, 1.f / 256.f, -mu * mu);
            float rs  = rsqrtf(var + EPSF);
            float nm  = -mu * rs;
            float acc = 0.f;
#pragma unroll
            for (int k = 0; k < 8; k++) {
                float hn = fmaf(fmaf(s[k], rs, nm), gm[k], bt[k]);
                float e  = __expf(fminf(hn, 0.f)) - 1.f;
                float v  = fmaxf(hn, 0.f) + e;
                acc = fmaf(v, w2r[k], acc);
            }
            acc = warp_sum(acc);
            if (lane == 0) out[i * NN + j] = acc + b2[0];
        }
        return;
    }

    // ================= main tile path =================
    extern __shared__ __align__(16) char smem_raw[];
    u64 (*sA)[128] = reinterpret_cast<u64(*)[128]>(smem_raw + SA_OFF);
    u64 (*sB)[33]  = reinterpret_cast<u64(*)[33]>(smem_raw + SB_OFF);
    u64 (*sGB)[2]  = reinterpret_cast<u64(*)[2]>(smem_raw + SGB_OFF);
    u64 (*sW)[2]   = reinterpret_cast<u64(*)[2]>(smem_raw + SW_OFF);
    float* sSA = reinterpret_cast<float*>(smem_raw + SSA_OFF);
    float* sSB = reinterpret_cast<float*>(smem_raw + SSB_OFF);
    float* sQA = reinterpret_cast<float*>(smem_raw + SQA_OFF);
    float* sQB = reinterpret_cast<float*>(smem_raw + SQB_OFF);

    const int i0 = (blockIdx.x >> 4) * 32, j0 = (blockIdx.x & 15) * 32;
    const float L2E  = 1.4426950408889634f;
    const float IL2E = 0.6931471805599453f;

    {
        const u64* gA = reinterpret_cast<const u64*>(g_RA) + i0 * 128;
#pragma unroll
        for (int k = 0; k < 16; k++) {
            int idx = t + 256 * k;
            sA[idx >> 7][idx & 127] = gA[idx];
        }
    }
    {
        const u64* gB = reinterpret_cast<const u64*>(g_RB) + j0 * 128;
        int j = t >> 3, part = t & 7;
#pragma unroll
        for (int k = 0; k < 16; k++) {
            int c2 = part + 8 * k;
            sB[c2][j] = gB[j * 128 + c2];
        }
    }
    if (t < 128) {
        float2 gv = reinterpret_cast<const float2*>(gamma)[t];
        float2 bv = reinterpret_cast<const float2*>(beta)[t];
        float2 wv = reinterpret_cast<const float2*>(W2)[t];
        sGB[t][0] = pk(gv.x * L2E, gv.y * L2E);
        sGB[t][1] = pk(bv.x * L2E, bv.y * L2E);
        sW [t][0] = pk(wv.x * IL2E, wv.y * IL2E);
        sW [t][1] = pk(wv.x, wv.y);
    } else if (t < 160) {
        sSA[t - 128] = g_SA[i0 + t - 128];
    } else if (t < 192) {
        sSB[t - 160] = g_SB[j0 + t - 160];
    } else if (t < 224) {
        sQA[t - 192] = g_QA[i0 + t - 192];
    } else {
        sQB[t - 224] = g_QB[j0 + t - 224];
    }
    const float CADD = b2[0] - g_CW;
    __syncthreads();

    const int r0 = 4 * w;

    // ---- pass 1: cross-dot X[r] = sum_c RA*RB (packed) ----
    u64 xd[4] = {0, 0, 0, 0};
#pragma unroll 8
    for (int c2 = 0; c2 < 128; c2++) {
        u64 bv = sB[c2][lane];
#pragma unroll
        for (int r = 0; r < 4; r++)
            xd[r] = fma2(sA[r0 + r][c2], bv, xd[r]);
    }
    u64 rs2[4], nm2[4];
#pragma unroll
    for (int r = 0; r < 4; r++) {
        float xl_, xh_; unpk(xd[r], xl_, xh_);
        float sq  = sQA[r0 + r] + sQB[lane] + 2.f * (xl_ + xh_);
        float sum = sSA[r0 + r] + sSB[lane];
        float mu  = sum * (1.f / 256.f);
        float var = fmaf(sq, 1.f / 256.f, -mu * mu);
        float rs  = rsqrtf(var + EPSF);
        rs2[r] = pk(rs, rs);
        float nm = -mu * rs;
        nm2[r] = pk(nm, nm);
    }

    // ---- pass 2: CELU (log2e domain) + dot(W2) ----
    u64 am[4] = {0, 0, 0, 0}, ae[4] = {0, 0, 0, 0};
#pragma unroll 4
    for (int c2 = 0; c2 < 128; c2++) {
        u64 bv = sB[c2][lane];
        ulonglong2 gb = *reinterpret_cast<const ulonglong2*>(sGB[c2]);
        ulonglong2 wv = *reinterpret_cast<const ulonglong2*>(sW[c2]);
#pragma unroll
        for (int r = 0; r < 4; r++) {
            u64 s = add2(sA[r0 + r][c2], bv);
            u64 h = fma2(fma2(s, rs2[r], nm2[r]), gb.x, gb.y);
            float hl, hh; unpk(h, hl, hh);
            float el = ex2f(fminf(hl, 0.f));
            float eh = ex2f(fminf(hh, 0.f));
            float ml = fmaxf(hl, 0.f);
            float mh = fmaxf(hh, 0.f);
            am[r] = fma2(pk(ml, mh), wv.x, am[r]);
            ae[r] = fma2(pk(el, eh), wv.y, ae[r]);
        }
    }

    const int gj = j0 + lane;
    const bool jint = (gj != 0) && (gj != NN - 1);
#pragma unroll
    for (int r = 0; r < 4; r++) {
        int gi = i0 + r0 + r;
        if (jint && gi != 0 && gi != NN - 1) {
            float a, b; unpk(add2(am[r], ae[r]), a, b);
            out[gi * NN + gj] = (a + b) + CADD;
        }
    }
}

// ---------------------------------------------------------------------------
extern "C" void kernel_launch(void* const* d_in, const int* in_sizes, int n_in,
                              void* d_out, int out_size)
{
    const float* xl    = (const float*)d_in[0];
    const float* xr    = (const float*)d_in[1];
    const float* W1    = (const float*)d_in[2];
    const float* b1    = (const float*)d_in[3];
    const float* gamma = (const float*)d_in[4];
    const float* beta  = (const float*)d_in[5];
    const float* W2    = (const float*)d_in[6];
    const float* b2    = (const float*)d_in[7];
    float* out = (float*)d_out;

    static bool attr_set = false;
    if (!attr_set) {
        cudaFuncSetAttribute(pair_fused_kernel,
                             cudaFuncAttributeMaxDynamicSharedMemorySize, SMEM_SZ);
        attr_set = true;
    }

    dim3 gpre(16, 24, 2);
    gemm_pre_kernel<<<gpre, 128>>>(xl, xr, W1);
    combine_kernel<<<NN, 256>>>(b1, W2);
    pair_fused_kernel<<<256 + 32, 256, SMEM_SZ>>>(gamma, beta, W2, b2, out);
}

// round 9
// speedup vs baseline: 1.4785x; 1.0423x over previous
#include <cuda_runtime.h>

#define NN 512
#define CC 64
#define HH 256
#define EPSF 1e-5f

typedef unsigned long long u64;

// ---------------- packed f32x2 helpers (verified on sm_103a) ----------------
__device__ __forceinline__ u64 pk(float lo, float hi) {
    u64 r; asm("mov.b64 %0,{%1,%2};" : "=l"(r) : "f"(lo), "f"(hi)); return r;
}
__device__ __forceinline__ void unpk(u64 v, float& lo, float& hi) {
    asm("mov.b64 {%0,%1},%2;" : "=f"(lo), "=f"(hi) : "l"(v));
}
__device__ __forceinline__ u64 add2(u64 a, u64 b) {
    u64 r; asm("add.rn.f32x2 %0,%1,%2;" : "=l"(r) : "l"(a), "l"(b)); return r;
}
__device__ __forceinline__ u64 fma2(u64 a, u64 b, u64 c) {
    u64 r; asm("fma.rn.f32x2 %0,%1,%2,%3;" : "=l"(r) : "l"(a), "l"(b), "l"(c)); return r;
}
__device__ __forceinline__ float ex2f(float x) {
    float r; asm("ex2.approx.f32 %0,%1;" : "=f"(r) : "f"(x)); return r;
}
__device__ __forceinline__ float warp_sum(float x) {
#pragma unroll
    for (int off = 16; off > 0; off >>= 1)
        x += __shfl_xor_sync(0xffffffffu, x, off);
    return x;
}

// ---------------- scratch (device globals) ----------------
__device__ float g_T[2][NN][768];
__device__ float g_RA [NN*HH];
__device__ float g_RB [NN*HH];
__device__ float g_A1M[NN*HH];
__device__ float g_A2P[NN*HH];
__device__ float g_B1P[NN*HH];
__device__ float g_B2M[NN*HH];
__device__ float g_SA[NN];
__device__ float g_SB[NN];
__device__ float g_QA[NN];
__device__ float g_QB[NN];
__device__ float g_CW;

// ---------------------------------------------------------------------------
// Stage 1: GEMM, 32x32 tiles, 128 threads, pipelined k-loop.
// ---------------------------------------------------------------------------
__global__ __launch_bounds__(128) void gemm_pre_kernel(
    const float* __restrict__ xl, const float* __restrict__ xr,
    const float* __restrict__ W1)
{
    __shared__ float Xs[64][36];
    __shared__ float Ws[64][36];

    const int z  = blockIdx.z;
    const float* X = z ? xr : xl;
    const int m0 = blockIdx.x * 32;
    const int n0 = blockIdx.y * 32;
    const int sel = n0 >> 8;
    const int h0  = n0 & 255;
    const float* Wbase = W1 + ((2 * sel + z) * 64) * HH + h0;

    const int t = threadIdx.x;
    {
        int f = t & 63, i2 = t >> 6;
#pragma unroll
        for (int ii = 0; ii < 32; ii += 2)
            Xs[f][i2 + ii] = X[(m0 + i2 + ii) * CC + f];
    }
    {
        int n = t & 31, f0 = t >> 5;
#pragma unroll
        for (int ff = 0; ff < 64; ff += 4)
            Ws[f0 + ff][n] = Wbase[(f0 + ff) * HH + n];
    }
    __syncthreads();

    const int tx = t & 7, ty = t >> 3;
    u64 acc[2][2] = {};
    float2 xa = *reinterpret_cast<const float2*>(&Xs[0][2 * ty]);
    ulonglong2 wb = *reinterpret_cast<const ulonglong2*>(&Ws[0][4 * tx]);
#pragma unroll 16
    for (int k = 0; k < 64; k++) {
        const int kn = (k + 1) & 63;
        float2 xan = *reinterpret_cast<const float2*>(&Xs[kn][2 * ty]);
        ulonglong2 wbn = *reinterpret_cast<const ulonglong2*>(&Ws[kn][4 * tx]);
        u64 x0 = pk(xa.x, xa.x), x1 = pk(xa.y, xa.y);
        acc[0][0] = fma2(x0, wb.x, acc[0][0]);
        acc[0][1] = fma2(x0, wb.y, acc[0][1]);
        acc[1][0] = fma2(x1, wb.x, acc[1][0]);
        acc[1][1] = fma2(x1, wb.y, acc[1][1]);
        xa = xan; wb = wbn;
    }
#pragma unroll
    for (int r = 0; r < 2; r++) {
        float a, b, c, d;
        unpk(acc[r][0], a, b);
        unpk(acc[r][1], c, d);
        *reinterpret_cast<float4*>(&g_T[z][m0 + 2 * ty + r][n0 + 4 * tx]) =
            make_float4(a, b, c, d);
    }
}

// ---------------------------------------------------------------------------
// Stage 2: combine shifts + b1 into RA/RB (+masked parts), row sums SA/SB,
// row sums-of-squares QA/QB, W2 total.
// ---------------------------------------------------------------------------
__global__ __launch_bounds__(256) void combine_kernel(
    const float* __restrict__ b1, const float* __restrict__ W2)
{
    __shared__ float smA[8], smB[8], smW[8], smQA[8], smQB[8];
    const int i = blockIdx.x, h = threadIdx.x;
    const int lane = h & 31, w = h >> 5;

    float a0  = g_T[0][i][h];
    float a1m = (i > 0)      ? g_T[0][i - 1][256 + h] : 0.f;
    float a2p = (i < NN - 1) ? g_T[0][i + 1][512 + h] : 0.f;
    float ra  = a0 + b1[h] + a1m + a2p;
    g_A1M[i * HH + h] = a1m;
    g_A2P[i * HH + h] = a2p;
    g_RA [i * HH + h] = ra;

    float b0  = g_T[1][i][h];
    float b1p = (i < NN - 1) ? g_T[1][i + 1][256 + h] : 0.f;
    float b2m = (i > 0)      ? g_T[1][i - 1][512 + h] : 0.f;
    float rb  = b0 + b1p + b2m;
    g_B1P[i * HH + h] = b1p;
    g_B2M[i * HH + h] = b2m;
    g_RB [i * HH + h] = rb;

    float sa = warp_sum(ra);
    float sb = warp_sum(rb);
    float qa = warp_sum(ra * ra);
    float qb = warp_sum(rb * rb);
    float sw = warp_sum((i == 0) ? W2[h] : 0.f);
    if (lane == 0) { smA[w] = sa; smB[w] = sb; smQA[w] = qa; smQB[w] = qb; smW[w] = sw; }
    __syncthreads();
    if (h == 0) {
        float ta = 0.f, tb = 0.f, tqa = 0.f, tqb = 0.f, tw = 0.f;
#pragma unroll
        for (int k = 0; k < 8; k++) {
            ta += smA[k]; tb += smB[k]; tqa += smQA[k]; tqb += smQB[k]; tw += smW[k];
        }
        g_SA[i] = ta; g_SB[i] = tb;
        g_QA[i] = tqa; g_QB[i] = tqb;
        if (i == 0) g_CW = tw;
    }
}

// ---------------------------------------------------------------------------
// Stage 3: fused kernel. Blocks 0..255: 32x32 tile, R=4 rows/thread,
// software-pipelined LDS. Blocks 256..287: border fixup.
// ---------------------------------------------------------------------------
#define SA_OFF   0
#define SB_OFF   32768
#define SGB_OFF  66560
#define SW_OFF   68608
#define SSA_OFF  70656
#define SSB_OFF  70784
#define SQA_OFF  70912
#define SQB_OFF  71040
#define SMEM_SZ  71168

__global__ __launch_bounds__(256, 3) void pair_fused_kernel(
    const float* __restrict__ gamma, const float* __restrict__ beta,
    const float* __restrict__ W2, const float* __restrict__ b2,
    float* __restrict__ out)
{
    const int t = threadIdx.x;
    const int lane = t & 31, w = t >> 5;

    if (blockIdx.x >= 256) {
        // ================= fixup path =================
        const int fb = blockIdx.x - 256;
#pragma unroll 1
        for (int c = 0; c < 8; c++) {
            const int gw = fb * 8 + w + 256 * c;
            const int side = gw >> 9, pos = gw & 511;
            int i, j;
            if      (side == 0) { i = 0;      j = pos; }
            else if (side == 1) { i = NN - 1; j = pos; }
            else if (side == 2) { i = pos;    j = 0; }
            else                { i = pos;    j = NN - 1; }

            const bool mi0 = (i == 0), mi1 = (i == NN - 1);
            const bool mj0 = (j == 0), mj1 = (j == NN - 1);
            const float4 z4 = make_float4(0.f, 0.f, 0.f, 0.f);

            const float4* RA4 = reinterpret_cast<const float4*>(g_RA)  + i * 64;
            const float4* RB4 = reinterpret_cast<const float4*>(g_RB)  + j * 64;
            const float4* BP4 = reinterpret_cast<const float4*>(g_B1P) + j * 64;
            const float4* BM4 = reinterpret_cast<const float4*>(g_B2M) + j * 64;
            const float4* AP4 = reinterpret_cast<const float4*>(g_A2P) + i * 64;
            const float4* AM4 = reinterpret_cast<const float4*>(g_A1M) + i * 64;

            float s[8], gm[8], bt[8], w2r[8];
#pragma unroll
            for (int half = 0; half < 2; half++) {
                int idx = lane + 32 * half;
                float4 ra = RA4[idx];
                float4 rb = RB4[idx];
                float4 c1 = mi0 ? BP4[idx] : z4;
                float4 c2 = mi1 ? BM4[idx] : z4;
                float4 c3 = mj0 ? AP4[idx] : z4;
                float4 c4 = mj1 ? AM4[idx] : z4;
                int o = 4 * half;
                s[o + 0] = ra.x + rb.x - c1.x - c2.x - c3.x - c4.x;
                s[o + 1] = ra.y + rb.y - c1.y - c2.y - c3.y - c4.y;
                s[o + 2] = ra.z + rb.z - c1.z - c2.z - c3.z - c4.z;
                s[o + 3] = ra.w + rb.w - c1.w - c2.w - c3.w - c4.w;
                float4 gv = reinterpret_cast<const float4*>(gamma)[idx];
                float4 bv = reinterpret_cast<const float4*>(beta )[idx];
                float4 wv = reinterpret_cast<const float4*>(W2   )[idx];
                gm[o] = gv.x; gm[o+1] = gv.y; gm[o+2] = gv.z; gm[o+3] = gv.w;
                bt[o] = bv.x; bt[o+1] = bv.y; bt[o+2] = bv.z; bt[o+3] = bv.w;
                w2r[o] = wv.x; w2r[o+1] = wv.y; w2r[o+2] = wv.z; w2r[o+3] = wv.w;
            }

            float sum = ((s[0] + s[1]) + (s[2] + s[3])) + ((s[4] + s[5]) + (s[6] + s[7]));
            float sq  = fmaf(s[0], s[0], s[1] * s[1]);
            sq = fmaf(s[2], s[2], fmaf(s[3], s[3], sq));
            sq = fmaf(s[4], s[4], sq);
            sq = fmaf(s[5], s[5], sq);
            sq = fmaf(s[6], s[6], fmaf(s[7], s[7], sq));
            sum = warp_sum(sum);
            sq  = warp_sum(sq);

            float mu  = sum * (1.f / 256.f);
            float var = fmaf(sq, 1.f / 256.f, -mu * mu);
            float rs  = rsqrtf(var + EPSF);
            float nm  = -mu * rs;
            float acc = 0.f;
#pragma unroll
            for (int k = 0; k < 8; k++) {
                float hn = fmaf(fmaf(s[k], rs, nm), gm[k], bt[k]);
                float e  = __expf(fminf(hn, 0.f)) - 1.f;
                float v  = fmaxf(hn, 0.f) + e;
                acc = fmaf(v, w2r[k], acc);
            }
            acc = warp_sum(acc);
            if (lane == 0) out[i * NN + j] = acc + b2[0];
        }
        return;
    }

    // ================= main tile path =================
    extern __shared__ __align__(16) char smem_raw[];
    u64 (*sA)[128] = reinterpret_cast<u64(*)[128]>(smem_raw + SA_OFF);
    u64 (*sB)[33]  = reinterpret_cast<u64(*)[33]>(smem_raw + SB_OFF);
    u64 (*sGB)[2]  = reinterpret_cast<u64(*)[2]>(smem_raw + SGB_OFF);
    u64 (*sW)[2]   = reinterpret_cast<u64(*)[2]>(smem_raw + SW_OFF);
    float* sSA = reinterpret_cast<float*>(smem_raw + SSA_OFF);
    float* sSB = reinterpret_cast<float*>(smem_raw + SSB_OFF);
    float* sQA = reinterpret_cast<float*>(smem_raw + SQA_OFF);
    float* sQB = reinterpret_cast<float*>(smem_raw + SQB_OFF);

    const int i0 = (blockIdx.x >> 4) * 32, j0 = (blockIdx.x & 15) * 32;
    const float L2E  = 1.4426950408889634f;
    const float IL2E = 0.6931471805599453f;

    {
        const u64* gA = reinterpret_cast<const u64*>(g_RA) + i0 * 128;
#pragma unroll
        for (int k = 0; k < 16; k++) {
            int idx = t + 256 * k;
            sA[idx >> 7][idx & 127] = gA[idx];
        }
    }
    {
        const u64* gB = reinterpret_cast<const u64*>(g_RB) + j0 * 128;
        int j = t >> 3, part = t & 7;
#pragma unroll
        for (int k = 0; k < 16; k++) {
            int c2 = part + 8 * k;
            sB[c2][j] = gB[j * 128 + c2];
        }
    }
    if (t < 128) {
        float2 gv = reinterpret_cast<const float2*>(gamma)[t];
        float2 bv = reinterpret_cast<const float2*>(beta)[t];
        float2 wv = reinterpret_cast<const float2*>(W2)[t];
        sGB[t][0] = pk(gv.x * L2E, gv.y * L2E);
        sGB[t][1] = pk(bv.x * L2E, bv.y * L2E);
        sW [t][0] = pk(wv.x * IL2E, wv.y * IL2E);
        sW [t][1] = pk(wv.x, wv.y);
    } else if (t < 160) {
        sSA[t - 128] = g_SA[i0 + t - 128];
    } else if (t < 192) {
        sSB[t - 160] = g_SB[j0 + t - 160];
    } else if (t < 224) {
        sQA[t - 192] = g_QA[i0 + t - 192];
    } else {
        sQB[t - 224] = g_QB[j0 + t - 224];
    }
    const float CADD = b2[0] - g_CW;
    __syncthreads();

    const int r0 = 4 * w;

    // ---- pass 1: cross-dot X[r] = sum_c RA*RB (packed, pipelined) ----
    u64 xd[4] = {0, 0, 0, 0};
    {
        u64 bv = sB[0][lane];
#pragma unroll 8
        for (int c2 = 0; c2 < 128; c2++) {
            u64 bvn = sB[(c2 + 1) & 127][lane];
#pragma unroll
            for (int r = 0; r < 4; r++)
                xd[r] = fma2(sA[r0 + r][c2], bv, xd[r]);
            bv = bvn;
        }
    }
    u64 rs2[4], nm2[4];
#pragma unroll
    for (int r = 0; r < 4; r++) {
        float xl_, xh_; unpk(xd[r], xl_, xh_);
        float sq  = sQA[r0 + r] + sQB[lane] + 2.f * (xl_ + xh_);
        float sum = sSA[r0 + r] + sSB[lane];
        float mu  = sum * (1.f / 256.f);
        float var = fmaf(sq, 1.f / 256.f, -mu * mu);
        float rs  = rsqrtf(var + EPSF);
        rs2[r] = pk(rs, rs);
        float nm = -mu * rs;
        nm2[r] = pk(nm, nm);
    }

    // ---- pass 2: CELU (log2e domain) + dot(W2), pipelined ----
    u64 am[4] = {0, 0, 0, 0}, ae[4] = {0, 0, 0, 0};
    {
        u64 bv = sB[0][lane];
        ulonglong2 gb = *reinterpret_cast<const ulonglong2*>(sGB[0]);
        ulonglong2 wv = *reinterpret_cast<const ulonglong2*>(sW[0]);
#pragma unroll 4
        for (int c2 = 0; c2 < 128; c2++) {
            const int cn = (c2 + 1) & 127;
            u64 bvn = sB[cn][lane];
            ulonglong2 gbn = *reinterpret_cast<const ulonglong2*>(sGB[cn]);
            ulonglong2 wvn = *reinterpret_cast<const ulonglong2*>(sW[cn]);
#pragma unroll
            for (int r = 0; r < 4; r++) {
                u64 s = add2(sA[r0 + r][c2], bv);
                u64 h = fma2(fma2(s, rs2[r], nm2[r]), gb.x, gb.y);
                float hl, hh; unpk(h, hl, hh);
                float el = ex2f(fminf(hl, 0.f));
                float eh = ex2f(fminf(hh, 0.f));
                float ml = fmaxf(hl, 0.f);
                float mh = fmaxf(hh, 0.f);
                am[r] = fma2(pk(ml, mh), wv.x, am[r]);
                ae[r] = fma2(pk(el, eh), wv.y, ae[r]);
            }
            bv = bvn; gb = gbn; wv = wvn;
        }
    }

    const int gj = j0 + lane;
    const bool jint = (gj != 0) && (gj != NN - 1);
#pragma unroll
    for (int r = 0; r < 4; r++) {
        int gi = i0 + r0 + r;
        if (jint && gi != 0 && gi != NN - 1) {
            float a, b; unpk(add2(am[r], ae[r]), a, b);
            out[gi * NN + gj] = (a + b) + CADD;
        }
    }
}

// ---------------------------------------------------------------------------
extern "C" void kernel_launch(void* const* d_in, const int* in_sizes, int n_in,
                              void* d_out, int out_size)
{
    const float* xl    = (const float*)d_in[0];
    const float* xr    = (const float*)d_in[1];
    const float* W1    = (const float*)d_in[2];
    const float* b1    = (const float*)d_in[3];
    const float* gamma = (const float*)d_in[4];
    const float* beta  = (const float*)d_in[5];
    const float* W2    = (const float*)d_in[6];
    const float* b2    = (const float*)d_in[7];
    float* out = (float*)d_out;

    static bool attr_set = false;
    if (!attr_set) {
        cudaFuncSetAttribute(pair_fused_kernel,
                             cudaFuncAttributeMaxDynamicSharedMemorySize, SMEM_SZ);
        attr_set = true;
    }

    dim3 gpre(16, 24, 2);
    gemm_pre_kernel<<<gpre, 128>>>(xl, xr, W1);
    combine_kernel<<<NN, 256>>>(b1, W2);
    pair_fused_kernel<<<256 + 32, 256, SMEM_SZ>>>(gamma, beta, W2, b2, out);
}